// round 7
// baseline (speedup 1.0000x reference)
#include <cuda_runtime.h>
#include <math.h>

#define N_NODES 2000
#define N_EDGES 40000
#define NBT     128      // B * Tp = 4 * 32
#define C       32
#define XS      36       // padded x-tile stride (floats): 144B, 16B-aligned, conflict-free

typedef unsigned long long u64;

// ---- f32x2 packed helpers (FFMA2 path: only reachable via PTX) ----
__device__ __forceinline__ u64 pack2(float lo, float hi) {
    u64 d; asm("mov.b64 %0, {%1, %2};" : "=l"(d) : "f"(lo), "f"(hi)); return d;
}
__device__ __forceinline__ void unpack2(u64 v, float& lo, float& hi) {
    asm("mov.b64 {%0, %1}, %2;" : "=f"(lo), "=f"(hi) : "l"(v));
}
__device__ __forceinline__ u64 fma2(u64 a, u64 b, u64 c) {
    u64 d; asm("fma.rn.f32x2 %0, %1, %2, %3;" : "=l"(d) : "l"(a), "l"(b), "l"(c)); return d;
}

// ---- scratch (no allocations; __device__ globals) ----
__device__ __align__(16) float g_hw[(size_t)NBT * N_NODES * C];   // 32 MB
__device__ float g_invdeg[N_NODES];
__device__ int   g_off[N_NODES + 1];
__device__ int   g_src[N_EDGES];
__device__ float g_nrm[N_EDGES];

// ---- edge_index accessors (layout decided per-launch by block-wide OR) ----
__device__ __forceinline__ int edge_row(const void* ei, int e, int is64) {
    return is64 ? (int)((const long long*)ei)[e] : ((const int*)ei)[e];
}
__device__ __forceinline__ int edge_col(const void* ei, int e, int is64) {
    return is64 ? (int)((const long long*)ei)[N_EDGES + e]
                : ((const int*)ei)[N_EDGES + e];
}

// ------------------------------------------------------------------
// Fused CSR build: one block, 1024 threads, smem-resident deg/cnt/dis/cursors.
// Replaces k_deg + k_scan + k_fill (global atomics -> shared atomics, 1 launch).
__global__ void __launch_bounds__(1024) k_csr(const void* __restrict__ ei,
                                              const float* __restrict__ ew) {
    __shared__ float sdeg[N_NODES];
    __shared__ int   scnt[N_NODES];    // counts, then reused as fill cursors
    __shared__ float sdis[N_NODES];
    __shared__ int   wsum[32];
    int tid = threadIdx.x;
    int lane = tid & 31, wid = tid >> 5;

    for (int i = tid; i < N_NODES; i += 1024) { sdeg[i] = 1.0f; scnt[i] = 0; }

    // int64-vs-int32 layout detect: OR of hi/odd words (int64 ids<2000 => 0)
    int nz = 0;
    const int* wp = (const int*)ei;
    for (int e = tid; e < N_EDGES; e += 1024)
        nz |= wp[2 * e + 1] | wp[2 * (N_EDGES + e) + 1];
    int is64 = !__syncthreads_or(nz);          // also orders the init above

    // degree accumulation (shared atomics)
    for (int e = tid; e < N_EDGES; e += 1024) {
        int c = edge_col(ei, e, is64);
        if ((unsigned)c < N_NODES) {
            atomicAdd(&sdeg[c], ew[e]);
            atomicAdd(&scnt[c], 1);
        }
    }
    __syncthreads();

    for (int i = tid; i < N_NODES; i += 1024) {
        float d = sdeg[i];                     // >= 1 (self loop)
        sdis[i] = rsqrtf(d);
        g_invdeg[i] = 1.0f / d;                // self-loop norm = dis*dis
    }

    // exclusive scan of scnt (2000 elems, 2 per thread)
    int base = tid * 2;
    int c0 = (base     < N_NODES) ? scnt[base]     : 0;
    int c1 = (base + 1 < N_NODES) ? scnt[base + 1] : 0;
    int tot = c0 + c1;
    int incl = tot;
    #pragma unroll
    for (int d = 1; d < 32; d <<= 1) {
        int n = __shfl_up_sync(0xffffffffu, incl, d);
        if (lane >= d) incl += n;
    }
    if (lane == 31) wsum[wid] = incl;
    __syncthreads();                            // also: all scnt reads done
    if (tid < 32) {
        int v = wsum[tid];
        int i2 = v;
        #pragma unroll
        for (int d = 1; d < 32; d <<= 1) {
            int n = __shfl_up_sync(0xffffffffu, i2, d);
            if (tid >= d) i2 += n;
        }
        wsum[tid] = i2 - v;                     // exclusive warp offsets
        if (tid == 31) g_off[N_NODES] = i2;     // inclusive total
    }
    __syncthreads();
    int off = wsum[wid] + (incl - tot);
    if (base < N_NODES)     { g_off[base]     = off;      scnt[base]     = off; }
    if (base + 1 < N_NODES) { g_off[base + 1] = off + c0; scnt[base + 1] = off + c0; }
    __syncthreads();

    // fill CSR (shared cursor atomics, scattered global stores)
    for (int e = tid; e < N_EDGES; e += 1024) {
        int r = edge_row(ei, e, is64);
        int c = edge_col(ei, e, is64);
        if ((unsigned)r < N_NODES && (unsigned)c < N_NODES) {
            int p = atomicAdd(&scnt[c], 1);
            if ((unsigned)p < N_EDGES) {
                g_src[p] = r;
                g_nrm[p] = sdis[r] * ew[e] * sdis[c];
            }
        }
    }
}

// ------------------------------------------------------------------
// Fused gated temporal conv + GCN weight matmul, FFMA2 version.
// Block: 128 threads, tile = 128 rows x 32 cols, one bt per blockIdx.y.
// Thread = 4 rows x 8 cols (4 f32x2 pairs). k chunked by 4: x read as
// register-cached float4 (LDS.128, conflict-free at stride 36).
__global__ void __launch_bounds__(128) k_conv(
                       const float* __restrict__ x,
                       const float* __restrict__ w1, const float* __restrict__ b1,
                       const float* __restrict__ w2, const float* __restrict__ b2,
                       const float* __restrict__ gw) {
    extern __shared__ float sm[];
    float* xs0 = sm;                    // 128*XS
    float* xs2 = sm + 128 * XS;         // 128*XS
    float* w1a = xs2 + 128 * XS;        // [k][o], 1024 each
    float* w1b = w1a + 1024;
    float* w2a = w1b + 1024;
    float* w2b = w2a + 1024;
    float* gws = w2b + 1024;            // gcn_w [d][e]
    __shared__ __align__(16) float bs1[32];
    __shared__ __align__(16) float bs2[32];

    int bt = blockIdx.y;
    int b = bt >> 5, t = bt & 31;
    int n0 = blockIdx.x * 128;
    int nrows = N_NODES - n0; if (nrows > 128) nrows = 128;
    int tid = threadIdx.x;

    for (int i = tid; i < 1024; i += 128) {
        int o = i & 31, cc = i >> 5;
        w1a[cc * 32 + o] = w1[o * 64 + cc * 2 + 0];
        w1b[cc * 32 + o] = w1[o * 64 + cc * 2 + 1];
        w2a[cc * 32 + o] = w2[o * 64 + cc * 2 + 0];
        w2b[cc * 32 + o] = w2[o * 64 + cc * 2 + 1];
        gws[i] = gw[i];
    }
    if (tid < 32) { bs1[tid] = b1[tid]; bs2[tid] = b2[tid]; }

    // x load: LDG.128 -> STS.128 at padded stride
    const float4* x0v = (const float4*)(x + ((size_t)(b * 34 + t)     * N_NODES + n0) * C);
    const float4* x2v = (const float4*)(x + ((size_t)(b * 34 + t + 2) * N_NODES + n0) * C);
    int nvec = nrows * 8;               // float4s per array
    for (int i = tid; i < nvec; i += 128) {
        int r = i >> 3, c4 = (i & 7) * 4;
        *(float4*)&xs0[r * XS + c4] = x0v[i];
        *(float4*)&xs2[r * XS + c4] = x2v[i];
    }
    __syncthreads();

    int cg = tid & 3;          // column group (8 cols = 4 pairs)
    int rt = tid >> 2;         // 0..31
    int r0 = rt * 4;           // 4 rows per thread
    int co = cg * 8;

    u64 acc1[4][4], acc2[4][4];
    {
        const u64* bp1 = (const u64*)&bs1[co];
        const u64* bp2 = (const u64*)&bs2[co];
        #pragma unroll
        for (int p = 0; p < 4; p++) {
            u64 v1 = bp1[p], v2 = bp2[p];
            #pragma unroll
            for (int r = 0; r < 4; r++) { acc1[r][p] = v1; acc2[r][p] = v2; }
        }
    }

    for (int kc = 0; kc < 8; kc++) {           // k chunk of 4 (body stays in L0 I$)
        float xa4[4][4], xb4[4][4];
        #pragma unroll
        for (int r = 0; r < 4; r++) {
            float4 ta = *(const float4*)&xs0[(r0 + r) * XS + kc * 4];
            xa4[r][0] = ta.x; xa4[r][1] = ta.y; xa4[r][2] = ta.z; xa4[r][3] = ta.w;
            float4 tb = *(const float4*)&xs2[(r0 + r) * XS + kc * 4];
            xb4[r][0] = tb.x; xb4[r][1] = tb.y; xb4[r][2] = tb.z; xb4[r][3] = tb.w;
        }
        #pragma unroll
        for (int kk = 0; kk < 4; kk++) {
            int k = kc * 4 + kk;
            const int wb = k * 32 + co;
            u64 xa[4], xb[4];
            #pragma unroll
            for (int r = 0; r < 4; r++) {
                xa[r] = pack2(xa4[r][kk], xa4[r][kk]);
                xb[r] = pack2(xb4[r][kk], xb4[r][kk]);
            }
            {
                ulonglong2 wlo = *(const ulonglong2*)&w1a[wb];
                ulonglong2 whi = *(const ulonglong2*)&w1a[wb + 4];
                u64 wv[4] = {wlo.x, wlo.y, whi.x, whi.y};
                #pragma unroll
                for (int r = 0; r < 4; r++)
                    #pragma unroll
                    for (int p = 0; p < 4; p++)
                        acc1[r][p] = fma2(xa[r], wv[p], acc1[r][p]);
                wlo = *(const ulonglong2*)&w1b[wb];
                whi = *(const ulonglong2*)&w1b[wb + 4];
                u64 uv[4] = {wlo.x, wlo.y, whi.x, whi.y};
                #pragma unroll
                for (int r = 0; r < 4; r++)
                    #pragma unroll
                    for (int p = 0; p < 4; p++)
                        acc1[r][p] = fma2(xb[r], uv[p], acc1[r][p]);
            }
            {
                ulonglong2 wlo = *(const ulonglong2*)&w2a[wb];
                ulonglong2 whi = *(const ulonglong2*)&w2a[wb + 4];
                u64 wv[4] = {wlo.x, wlo.y, whi.x, whi.y};
                #pragma unroll
                for (int r = 0; r < 4; r++)
                    #pragma unroll
                    for (int p = 0; p < 4; p++)
                        acc2[r][p] = fma2(xa[r], wv[p], acc2[r][p]);
                wlo = *(const ulonglong2*)&w2b[wb];
                whi = *(const ulonglong2*)&w2b[wb + 4];
                u64 uv[4] = {wlo.x, wlo.y, whi.x, whi.y};
                #pragma unroll
                for (int r = 0; r < 4; r++)
                    #pragma unroll
                    for (int p = 0; p < 4; p++)
                        acc2[r][p] = fma2(xb[r], uv[p], acc2[r][p]);
            }
        }
    }

    __syncthreads();                 // xs0/xs2 reads done; reuse xs0 as g-tile
    // g = tanh(a1) * sigmoid(a2); write as STS.128 rows
    #pragma unroll
    for (int r = 0; r < 4; r++) {
        float gv[8];
        #pragma unroll
        for (int p = 0; p < 4; p++) {
            float a0, a1v, c0, c1;
            unpack2(acc1[r][p], a0, a1v);
            unpack2(acc2[r][p], c0, c1);
            float th0 = 2.0f / (1.0f + __expf(-2.0f * a0)) - 1.0f;
            float th1 = 2.0f / (1.0f + __expf(-2.0f * a1v)) - 1.0f;
            float sg0 = 1.0f / (1.0f + __expf(-c0));
            float sg1 = 1.0f / (1.0f + __expf(-c1));
            gv[2 * p]     = th0 * sg0;
            gv[2 * p + 1] = th1 * sg1;
        }
        *(float4*)&xs0[(r0 + r) * XS + co]     = make_float4(gv[0], gv[1], gv[2], gv[3]);
        *(float4*)&xs0[(r0 + r) * XS + co + 4] = make_float4(gv[4], gv[5], gv[6], gv[7]);
    }
    __syncthreads();

    u64 hacc[4][4];
    u64 z = pack2(0.0f, 0.0f);
    #pragma unroll
    for (int r = 0; r < 4; r++)
        #pragma unroll
        for (int p = 0; p < 4; p++) hacc[r][p] = z;

    for (int kc = 0; kc < 8; kc++) {
        float gp4[4][4];
        #pragma unroll
        for (int r = 0; r < 4; r++) {
            float4 tg = *(const float4*)&xs0[(r0 + r) * XS + kc * 4];
            gp4[r][0] = tg.x; gp4[r][1] = tg.y; gp4[r][2] = tg.z; gp4[r][3] = tg.w;
        }
        #pragma unroll
        for (int kk = 0; kk < 4; kk++) {
            int k = kc * 4 + kk;
            u64 gp[4];
            #pragma unroll
            for (int r = 0; r < 4; r++) gp[r] = pack2(gp4[r][kk], gp4[r][kk]);
            ulonglong2 wlo = *(const ulonglong2*)&gws[k * 32 + co];
            ulonglong2 whi = *(const ulonglong2*)&gws[k * 32 + co + 4];
            u64 wv[4] = {wlo.x, wlo.y, whi.x, whi.y};
            #pragma unroll
            for (int r = 0; r < 4; r++)
                #pragma unroll
                for (int p = 0; p < 4; p++)
                    hacc[r][p] = fma2(gp[r], wv[p], hacc[r][p]);
        }
    }

    float* outp = g_hw + ((size_t)bt * N_NODES + n0) * C;
    #pragma unroll
    for (int r = 0; r < 4; r++) {
        int row = r0 + r;
        if (row < nrows) {
            ulonglong2 lo; lo.x = hacc[r][0]; lo.y = hacc[r][1];
            ulonglong2 hi; hi.x = hacc[r][2]; hi.y = hacc[r][3];
            *(ulonglong2*)&outp[row * 32 + co]     = lo;
            *(ulonglong2*)&outp[row * 32 + co + 4] = hi;
        }
    }
}

// ------------------------------------------------------------------
// Gather: warp per (bt, dst). lane = (half, channel-pair): half-warps process
// different edges (4 edges/iter/warp via 2 accs each), float2 loads, final
// shfl_xor(16) cross-half reduce. hw slice per bt (256KB) is L2-resident.
__global__ void k_gather(const float* __restrict__ gb, float* __restrict__ out) {
    int w = (blockIdx.x * blockDim.x + threadIdx.x) >> 5;
    if (w >= NBT * N_NODES) return;
    int lane = threadIdx.x & 31;
    int half = lane >> 4;           // 0 or 1
    int hl   = lane & 15;           // channel-pair index (ch = 2*hl, 2*hl+1)
    int bt  = w / N_NODES;
    int dst = w - bt * N_NODES;
    const float2* hb = (const float2*)(g_hw + (size_t)bt * (N_NODES * C));

    float2 acc0 = make_float2(0.0f, 0.0f);
    float2 acc1 = make_float2(0.0f, 0.0f);
    if (half == 0) {
        float2 bv = ((const float2*)gb)[hl];
        float idg = g_invdeg[dst];
        float2 sv = hb[dst * 16 + hl];
        acc0.x = bv.x + idg * sv.x;
        acc0.y = bv.y + idg * sv.y;
    }

    int s = g_off[dst], e = g_off[dst + 1];
    int i = s;
    for (; i + 3 < e; i += 4) {
        int ia = i + half * 2, ib = ia + 1;
        int   sa = g_src[ia]; float na = g_nrm[ia];
        int   sb = g_src[ib]; float nb = g_nrm[ib];
        float2 va = hb[sa * 16 + hl];
        float2 vb = hb[sb * 16 + hl];
        acc0.x += na * va.x; acc0.y += na * va.y;
        acc1.x += nb * vb.x; acc1.y += nb * vb.y;
    }
    for (; i + 1 < e; i += 2) {
        int ia = i + half;
        int sa = g_src[ia]; float na = g_nrm[ia];
        float2 va = hb[sa * 16 + hl];
        acc0.x += na * va.x; acc0.y += na * va.y;
    }
    if (i < e && half == 0) {
        int sa = g_src[i]; float na = g_nrm[i];
        float2 va = hb[sa * 16 + hl];
        acc0.x += na * va.x; acc0.y += na * va.y;
    }

    float rx = acc0.x + acc1.x;
    float ry = acc0.y + acc1.y;
    rx += __shfl_xor_sync(0xffffffffu, rx, 16);
    ry += __shfl_xor_sync(0xffffffffu, ry, 16);
    if (half == 0)
        ((float2*)out)[(size_t)w * 16 + hl] = make_float2(rx, ry);
}

// ------------------------------------------------------------------
extern "C" void kernel_launch(void* const* d_in, const int* in_sizes, int n_in,
                              void* d_out, int out_size) {
    const float* x  = (const float*)d_in[0];
    const void*  ei = d_in[1];                 // int64 OR int32 — detected on device
    const float* ew = (const float*)d_in[2];
    const float* w1 = (const float*)d_in[3];
    const float* b1 = (const float*)d_in[4];
    const float* w2 = (const float*)d_in[5];
    const float* b2 = (const float*)d_in[6];
    const float* gw = (const float*)d_in[7];
    const float* gb = (const float*)d_in[8];
    float* out = (float*)d_out;

    k_csr<<<1, 1024>>>(ei, ew);

    int smem = (2 * 128 * XS + 5 * 1024) * (int)sizeof(float);   // 57344 B
    cudaFuncSetAttribute(k_conv, cudaFuncAttributeMaxDynamicSharedMemorySize, smem);
    dim3 grid(16, NBT);
    k_conv<<<grid, 128, smem>>>(x, w1, b1, w2, b2, gw);

    int totw = NBT * N_NODES;                        // 256000 warps
    k_gather<<<(totw * 32 + 255) / 256, 256>>>(gb, out);
}

// round 8
// speedup vs baseline: 1.1669x; 1.1669x over previous
#include <cuda_runtime.h>
#include <math.h>

#define N_NODES 2000
#define N_EDGES 40000
#define NBT     128      // B * Tp = 4 * 32
#define C       32
#define XS      36       // padded x-tile stride (floats): 144B, 16B-aligned

typedef unsigned long long u64;

// ---- f32x2 packed helpers (FFMA2 path: only reachable via PTX) ----
__device__ __forceinline__ u64 pack2(float lo, float hi) {
    u64 d; asm("mov.b64 %0, {%1, %2};" : "=l"(d) : "f"(lo), "f"(hi)); return d;
}
__device__ __forceinline__ void unpack2(u64 v, float& lo, float& hi) {
    asm("mov.b64 {%0, %1}, %2;" : "=f"(lo), "=f"(hi) : "l"(v));
}
__device__ __forceinline__ u64 fma2(u64 a, u64 b, u64 c) {
    u64 d; asm("fma.rn.f32x2 %0, %1, %2, %3;" : "=l"(d) : "l"(a), "l"(b), "l"(c)); return d;
}

// ---- scratch (no allocations; __device__ globals, zero-init at load) ----
__device__ __align__(16) float g_hw[(size_t)NBT * N_NODES * C];   // 32 MB
__device__ float g_deg[N_NODES];     // MUST be 0 on entry (k_scan re-zeroes)
__device__ float g_dis[N_NODES];
__device__ float g_invdeg[N_NODES];
__device__ int   g_cnt[N_NODES];     // MUST be 0 on entry (k_scan re-zeroes)
__device__ int   g_off[N_NODES + 1];
__device__ int   g_cur[N_NODES];
__device__ int   g_src[N_EDGES];
__device__ float g_nrm[N_EDGES];

// Per-block int64-vs-int32 layout detection: OR of hi/odd words for this
// block's edges. int64 data (ids < 2000) => all zero. int32 => real ids.
__device__ __forceinline__ int detect_is64(const void* ei, int e, int valid) {
    int nz = 0;
    if (valid) {
        const int* w = (const int*)ei;
        nz = w[2 * e + 1] | w[2 * (N_EDGES + e) + 1];
    }
    return !__syncthreads_or(nz);
}
__device__ __forceinline__ int edge_row(const void* ei, int e, int is64) {
    return is64 ? (int)((const long long*)ei)[e] : ((const int*)ei)[e];
}
__device__ __forceinline__ int edge_col(const void* ei, int e, int is64) {
    return is64 ? (int)((const long long*)ei)[N_EDGES + e]
                : ((const int*)ei)[N_EDGES + e];
}

// ------------------------------------------------------------------
__global__ void k_deg(const void* __restrict__ ei, const float* __restrict__ ew) {
    int e = blockIdx.x * blockDim.x + threadIdx.x;
    int valid = (e < N_EDGES);
    int is64 = detect_is64(ei, e, valid);
    if (valid) {
        int c = edge_col(ei, e, is64);
        if ((unsigned)c < N_NODES) {
            atomicAdd(&g_deg[c], ew[e]);
            atomicAdd(&g_cnt[c], 1);
        }
    }
}

// single block, 256 threads: shfl-hierarchical exclusive scan + dis/invdeg.
// Consumes g_cnt/g_deg and re-zeroes them for the next kernel_launch call.
__global__ void k_scan() {
    __shared__ int wsum[8];
    int tid = threadIdx.x;
    int lane = tid & 31, wid = tid >> 5;

    int base = tid * 8;               // 256*8 = 2048 >= N_NODES
    int v[8];
    int tot = 0;
    #pragma unroll
    for (int j = 0; j < 8; j++) {
        int idx = base + j;
        int c = (idx < N_NODES) ? g_cnt[idx] : 0;
        v[j] = tot;                   // local exclusive prefix
        tot += c;
    }
    int incl = tot;
    #pragma unroll
    for (int d = 1; d < 32; d <<= 1) {
        int n = __shfl_up_sync(0xffffffffu, incl, d);
        if (lane >= d) incl += n;
    }
    if (lane == 31) wsum[wid] = incl;
    int texcl = incl - tot;
    __syncthreads();
    if (tid == 0) {
        int run = 0;
        #pragma unroll
        for (int w = 0; w < 8; w++) { int t = wsum[w]; wsum[w] = run; run += t; }
        g_off[N_NODES] = run;
    }
    __syncthreads();
    int off = wsum[wid] + texcl;
    #pragma unroll
    for (int j = 0; j < 8; j++) {
        int idx = base + j;
        if (idx < N_NODES) {
            int o = off + v[j];
            g_off[idx] = o; g_cur[idx] = o;
            g_cnt[idx] = 0;                    // reset for next call
        }
    }
    for (int i = tid; i < N_NODES; i += 256) {
        float d = 1.0f + g_deg[i];            // self-loop weight 1
        g_dis[i]    = rsqrtf(d);
        g_invdeg[i] = 1.0f / d;               // self-loop norm = dis*dis
        g_deg[i]    = 0.0f;                   // reset for next call
    }
}

__global__ void k_fill(const void* __restrict__ ei, const float* __restrict__ ew) {
    int e = blockIdx.x * blockDim.x + threadIdx.x;
    int valid = (e < N_EDGES);
    int is64 = detect_is64(ei, e, valid);
    if (valid) {
        int r = edge_row(ei, e, is64);
        int c = edge_col(ei, e, is64);
        if ((unsigned)r < N_NODES && (unsigned)c < N_NODES) {
            int p = atomicAdd(&g_cur[c], 1);
            if ((unsigned)p < N_EDGES) {
                g_src[p] = r;
                g_nrm[p] = g_dis[r] * ew[e] * g_dis[c];
            }
        }
    }
}

// ------------------------------------------------------------------
// Fused gated temporal conv + GCN weight matmul, FFMA2 version.
// Block: 256 threads (8 warps), tile = 128 rows x 32 cols, one bt per blockIdx.y.
// Thread = 2 rows x 8 cols (4 f32x2 pairs). 32 warps/SM (4 blocks x 8).
__global__ void __launch_bounds__(256) k_conv(
                       const float* __restrict__ x,
                       const float* __restrict__ w1, const float* __restrict__ b1,
                       const float* __restrict__ w2, const float* __restrict__ b2,
                       const float* __restrict__ gw) {
    extern __shared__ float sm[];
    float* xs0 = sm;                    // 128*XS
    float* xs2 = sm + 128 * XS;         // 128*XS
    float* w1a = xs2 + 128 * XS;        // [k][o], 1024 each
    float* w1b = w1a + 1024;
    float* w2a = w1b + 1024;
    float* w2b = w2a + 1024;
    float* gws = w2b + 1024;            // gcn_w [d][e]
    __shared__ __align__(16) float bs1[32];
    __shared__ __align__(16) float bs2[32];

    int bt = blockIdx.y;
    int b = bt >> 5, t = bt & 31;
    int n0 = blockIdx.x * 128;
    int nrows = N_NODES - n0; if (nrows > 128) nrows = 128;
    int tid = threadIdx.x;

    for (int i = tid; i < 1024; i += 256) {
        int o = i & 31, cc = i >> 5;
        w1a[cc * 32 + o] = w1[o * 64 + cc * 2 + 0];
        w1b[cc * 32 + o] = w1[o * 64 + cc * 2 + 1];
        w2a[cc * 32 + o] = w2[o * 64 + cc * 2 + 0];
        w2b[cc * 32 + o] = w2[o * 64 + cc * 2 + 1];
        gws[i] = gw[i];
    }
    if (tid < 32) { bs1[tid] = b1[tid]; bs2[tid] = b2[tid]; }

    // x load: LDG.128 -> STS.128 at padded stride
    const float4* x0v = (const float4*)(x + ((size_t)(b * 34 + t)     * N_NODES + n0) * C);
    const float4* x2v = (const float4*)(x + ((size_t)(b * 34 + t + 2) * N_NODES + n0) * C);
    int nvec = nrows * 8;               // float4s per array
    for (int i = tid; i < nvec; i += 256) {
        int r = i >> 3, c4 = (i & 7) * 4;
        *(float4*)&xs0[r * XS + c4] = x0v[i];
        *(float4*)&xs2[r * XS + c4] = x2v[i];
    }
    __syncthreads();

    int cg = tid & 3;          // column group (8 cols = 4 pairs)
    int rt = tid >> 2;         // 0..63
    int r0 = rt * 2;           // 2 rows per thread
    int co = cg * 8;

    u64 acc1[2][4], acc2[2][4];
    {
        const u64* bp1 = (const u64*)&bs1[co];
        const u64* bp2 = (const u64*)&bs2[co];
        #pragma unroll
        for (int p = 0; p < 4; p++) {
            u64 v1 = bp1[p], v2 = bp2[p];
            #pragma unroll
            for (int r = 0; r < 2; r++) { acc1[r][p] = v1; acc2[r][p] = v2; }
        }
    }

    for (int kc = 0; kc < 8; kc++) {           // k chunk of 4
        float xa4[2][4], xb4[2][4];
        #pragma unroll
        for (int r = 0; r < 2; r++) {
            float4 ta = *(const float4*)&xs0[(r0 + r) * XS + kc * 4];
            xa4[r][0] = ta.x; xa4[r][1] = ta.y; xa4[r][2] = ta.z; xa4[r][3] = ta.w;
            float4 tb = *(const float4*)&xs2[(r0 + r) * XS + kc * 4];
            xb4[r][0] = tb.x; xb4[r][1] = tb.y; xb4[r][2] = tb.z; xb4[r][3] = tb.w;
        }
        #pragma unroll
        for (int kk = 0; kk < 4; kk++) {
            int k = kc * 4 + kk;
            const int wb = k * 32 + co;
            u64 xa[2], xb[2];
            #pragma unroll
            for (int r = 0; r < 2; r++) {
                xa[r] = pack2(xa4[r][kk], xa4[r][kk]);
                xb[r] = pack2(xb4[r][kk], xb4[r][kk]);
            }
            {
                ulonglong2 wlo = *(const ulonglong2*)&w1a[wb];
                ulonglong2 whi = *(const ulonglong2*)&w1a[wb + 4];
                u64 wv[4] = {wlo.x, wlo.y, whi.x, whi.y};
                #pragma unroll
                for (int r = 0; r < 2; r++)
                    #pragma unroll
                    for (int p = 0; p < 4; p++)
                        acc1[r][p] = fma2(xa[r], wv[p], acc1[r][p]);
                wlo = *(const ulonglong2*)&w1b[wb];
                whi = *(const ulonglong2*)&w1b[wb + 4];
                u64 uv[4] = {wlo.x, wlo.y, whi.x, whi.y};
                #pragma unroll
                for (int r = 0; r < 2; r++)
                    #pragma unroll
                    for (int p = 0; p < 4; p++)
                        acc1[r][p] = fma2(xb[r], uv[p], acc1[r][p]);
            }
            {
                ulonglong2 wlo = *(const ulonglong2*)&w2a[wb];
                ulonglong2 whi = *(const ulonglong2*)&w2a[wb + 4];
                u64 wv[4] = {wlo.x, wlo.y, whi.x, whi.y};
                #pragma unroll
                for (int r = 0; r < 2; r++)
                    #pragma unroll
                    for (int p = 0; p < 4; p++)
                        acc2[r][p] = fma2(xa[r], wv[p], acc2[r][p]);
                wlo = *(const ulonglong2*)&w2b[wb];
                whi = *(const ulonglong2*)&w2b[wb + 4];
                u64 uv[4] = {wlo.x, wlo.y, whi.x, whi.y};
                #pragma unroll
                for (int r = 0; r < 2; r++)
                    #pragma unroll
                    for (int p = 0; p < 4; p++)
                        acc2[r][p] = fma2(xb[r], uv[p], acc2[r][p]);
            }
        }
    }

    __syncthreads();                 // xs0/xs2 reads done; reuse xs0 as g-tile
    // g = tanh(a1) * sigmoid(a2); write as STS.128 rows
    #pragma unroll
    for (int r = 0; r < 2; r++) {
        float gv[8];
        #pragma unroll
        for (int p = 0; p < 4; p++) {
            float a0, a1v, c0, c1;
            unpack2(acc1[r][p], a0, a1v);
            unpack2(acc2[r][p], c0, c1);
            float th0 = 2.0f / (1.0f + __expf(-2.0f * a0)) - 1.0f;
            float th1 = 2.0f / (1.0f + __expf(-2.0f * a1v)) - 1.0f;
            float sg0 = 1.0f / (1.0f + __expf(-c0));
            float sg1 = 1.0f / (1.0f + __expf(-c1));
            gv[2 * p]     = th0 * sg0;
            gv[2 * p + 1] = th1 * sg1;
        }
        *(float4*)&xs0[(r0 + r) * XS + co]     = make_float4(gv[0], gv[1], gv[2], gv[3]);
        *(float4*)&xs0[(r0 + r) * XS + co + 4] = make_float4(gv[4], gv[5], gv[6], gv[7]);
    }
    __syncthreads();

    u64 hacc[2][4];
    u64 z = pack2(0.0f, 0.0f);
    #pragma unroll
    for (int r = 0; r < 2; r++)
        #pragma unroll
        for (int p = 0; p < 4; p++) hacc[r][p] = z;

    for (int kc = 0; kc < 8; kc++) {
        float gp4[2][4];
        #pragma unroll
        for (int r = 0; r < 2; r++) {
            float4 tg = *(const float4*)&xs0[(r0 + r) * XS + kc * 4];
            gp4[r][0] = tg.x; gp4[r][1] = tg.y; gp4[r][2] = tg.z; gp4[r][3] = tg.w;
        }
        #pragma unroll
        for (int kk = 0; kk < 4; kk++) {
            int k = kc * 4 + kk;
            u64 gp[2];
            #pragma unroll
            for (int r = 0; r < 2; r++) gp[r] = pack2(gp4[r][kk], gp4[r][kk]);
            ulonglong2 wlo = *(const ulonglong2*)&gws[k * 32 + co];
            ulonglong2 whi = *(const ulonglong2*)&gws[k * 32 + co + 4];
            u64 wv[4] = {wlo.x, wlo.y, whi.x, whi.y};
            #pragma unroll
            for (int r = 0; r < 2; r++)
                #pragma unroll
                for (int p = 0; p < 4; p++)
                    hacc[r][p] = fma2(gp[r], wv[p], hacc[r][p]);
        }
    }

    float* outp = g_hw + ((size_t)bt * N_NODES + n0) * C;
    #pragma unroll
    for (int r = 0; r < 2; r++) {
        int row = r0 + r;
        if (row < nrows) {
            ulonglong2 lo; lo.x = hacc[r][0]; lo.y = hacc[r][1];
            ulonglong2 hi; hi.x = hacc[r][2]; hi.y = hacc[r][3];
            *(ulonglong2*)&outp[row * 32 + co]     = lo;
            *(ulonglong2*)&outp[row * 32 + co + 4] = hi;
        }
    }
}

// ------------------------------------------------------------------
// Gather: warp per (bt, dst). lane = (half, channel-pair): half-warps process
// different edges (4 edges/iter/warp via 2 accs each), float2 loads, final
// shfl_xor(16) cross-half reduce. hw slice per bt (256KB) is L2-resident.
__global__ void k_gather(const float* __restrict__ gb, float* __restrict__ out) {
    int w = (blockIdx.x * blockDim.x + threadIdx.x) >> 5;
    if (w >= NBT * N_NODES) return;
    int lane = threadIdx.x & 31;
    int half = lane >> 4;           // 0 or 1
    int hl   = lane & 15;           // channel-pair index (ch = 2*hl, 2*hl+1)
    int bt  = w / N_NODES;
    int dst = w - bt * N_NODES;
    const float2* hb = (const float2*)(g_hw + (size_t)bt * (N_NODES * C));

    float2 acc0 = make_float2(0.0f, 0.0f);
    float2 acc1 = make_float2(0.0f, 0.0f);
    if (half == 0) {
        float2 bv = ((const float2*)gb)[hl];
        float idg = g_invdeg[dst];
        float2 sv = hb[dst * 16 + hl];
        acc0.x = bv.x + idg * sv.x;
        acc0.y = bv.y + idg * sv.y;
    }

    int s = g_off[dst], e = g_off[dst + 1];
    int i = s;
    for (; i + 3 < e; i += 4) {
        int ia = i + half * 2, ib = ia + 1;
        int   sa = g_src[ia]; float na = g_nrm[ia];
        int   sb = g_src[ib]; float nb = g_nrm[ib];
        float2 va = hb[sa * 16 + hl];
        float2 vb = hb[sb * 16 + hl];
        acc0.x += na * va.x; acc0.y += na * va.y;
        acc1.x += nb * vb.x; acc1.y += nb * vb.y;
    }
    for (; i + 1 < e; i += 2) {
        int ia = i + half;
        int sa = g_src[ia]; float na = g_nrm[ia];
        float2 va = hb[sa * 16 + hl];
        acc0.x += na * va.x; acc0.y += na * va.y;
    }
    if (i < e && half == 0) {
        int sa = g_src[i]; float na = g_nrm[i];
        float2 va = hb[sa * 16 + hl];
        acc0.x += na * va.x; acc0.y += na * va.y;
    }

    float rx = acc0.x + acc1.x;
    float ry = acc0.y + acc1.y;
    rx += __shfl_xor_sync(0xffffffffu, rx, 16);
    ry += __shfl_xor_sync(0xffffffffu, ry, 16);
    if (half == 0)
        ((float2*)out)[(size_t)w * 16 + hl] = make_float2(rx, ry);
}

// ------------------------------------------------------------------
extern "C" void kernel_launch(void* const* d_in, const int* in_sizes, int n_in,
                              void* d_out, int out_size) {
    const float* x  = (const float*)d_in[0];
    const void*  ei = d_in[1];                 // int64 OR int32 — detected per-block
    const float* ew = (const float*)d_in[2];
    const float* w1 = (const float*)d_in[3];
    const float* b1 = (const float*)d_in[4];
    const float* w2 = (const float*)d_in[5];
    const float* b2 = (const float*)d_in[6];
    const float* gw = (const float*)d_in[7];
    const float* gb = (const float*)d_in[8];
    float* out = (float*)d_out;

    k_deg  <<<(N_EDGES + 255) / 256, 256>>>(ei, ew);
    k_scan <<<1, 256>>>();
    k_fill <<<(N_EDGES + 255) / 256, 256>>>(ei, ew);

    int smem = (2 * 128 * XS + 5 * 1024) * (int)sizeof(float);   // 57344 B
    cudaFuncSetAttribute(k_conv, cudaFuncAttributeMaxDynamicSharedMemorySize, smem);
    dim3 grid(16, NBT);
    k_conv<<<grid, 256, smem>>>(x, w1, b1, w2, b2, gw);

    int totw = NBT * N_NODES;                        // 256000 warps
    k_gather<<<(totw * 32 + 255) / 256, 256>>>(gb, out);
}

// round 9
// speedup vs baseline: 1.3828x; 1.1850x over previous
#include <cuda_runtime.h>
#include <math.h>

#define N_NODES 2000
#define N_EDGES 40000
#define NBT     128      // B * Tp = 4 * 32
#define C       32
#define XPS     65       // packed x-pair stride per k (float2 units), odd -> conflict-light

typedef unsigned long long u64;

// ---- f32x2 packed helpers (FFMA2 path: only reachable via PTX) ----
__device__ __forceinline__ u64 pack2(float lo, float hi) {
    u64 d; asm("mov.b64 %0, {%1, %2};" : "=l"(d) : "f"(lo), "f"(hi)); return d;
}
__device__ __forceinline__ void unpack2(u64 v, float& lo, float& hi) {
    asm("mov.b64 {%0, %1}, %2;" : "=f"(lo), "=f"(hi) : "l"(v));
}
__device__ __forceinline__ u64 fma2(u64 a, u64 b, u64 c) {
    u64 d; asm("fma.rn.f32x2 %0, %1, %2, %3;" : "=l"(d) : "l"(a), "l"(b), "l"(c)); return d;
}

// ---- scratch (no allocations; __device__ globals, zero-init at load) ----
__device__ __align__(16) float g_hw[(size_t)NBT * N_NODES * C];   // 32 MB
__device__ float g_deg[N_NODES];     // MUST be 0 on entry (k_scan re-zeroes)
__device__ float g_dis[N_NODES];
__device__ float g_invdeg[N_NODES];
__device__ int   g_cnt[N_NODES];     // MUST be 0 on entry (k_scan re-zeroes)
__device__ int   g_off[N_NODES + 1];
__device__ int   g_cur[N_NODES];
__device__ int   g_src[N_EDGES];
__device__ float g_nrm[N_EDGES];

// Per-block int64-vs-int32 layout detection: OR of hi/odd words for this
// block's edges. int64 data (ids < 2000) => all zero. int32 => real ids.
__device__ __forceinline__ int detect_is64(const void* ei, int e, int valid) {
    int nz = 0;
    if (valid) {
        const int* w = (const int*)ei;
        nz = w[2 * e + 1] | w[2 * (N_EDGES + e) + 1];
    }
    return !__syncthreads_or(nz);
}
__device__ __forceinline__ int edge_row(const void* ei, int e, int is64) {
    return is64 ? (int)((const long long*)ei)[e] : ((const int*)ei)[e];
}
__device__ __forceinline__ int edge_col(const void* ei, int e, int is64) {
    return is64 ? (int)((const long long*)ei)[N_EDGES + e]
                : ((const int*)ei)[N_EDGES + e];
}

// ------------------------------------------------------------------
__global__ void k_deg(const void* __restrict__ ei, const float* __restrict__ ew) {
    int e = blockIdx.x * blockDim.x + threadIdx.x;
    int valid = (e < N_EDGES);
    int is64 = detect_is64(ei, e, valid);
    if (valid) {
        int c = edge_col(ei, e, is64);
        if ((unsigned)c < N_NODES) {
            atomicAdd(&g_deg[c], ew[e]);
            atomicAdd(&g_cnt[c], 1);
        }
    }
}

// single block, 256 threads: shfl-hierarchical exclusive scan + dis/invdeg.
// Consumes g_cnt/g_deg and re-zeroes them for the next kernel_launch call.
__global__ void k_scan() {
    __shared__ int wsum[8];
    int tid = threadIdx.x;
    int lane = tid & 31, wid = tid >> 5;

    int base = tid * 8;               // 256*8 = 2048 >= N_NODES
    int v[8];
    int tot = 0;
    #pragma unroll
    for (int j = 0; j < 8; j++) {
        int idx = base + j;
        int c = (idx < N_NODES) ? g_cnt[idx] : 0;
        v[j] = tot;
        tot += c;
    }
    int incl = tot;
    #pragma unroll
    for (int d = 1; d < 32; d <<= 1) {
        int n = __shfl_up_sync(0xffffffffu, incl, d);
        if (lane >= d) incl += n;
    }
    if (lane == 31) wsum[wid] = incl;
    int texcl = incl - tot;
    __syncthreads();
    if (tid == 0) {
        int run = 0;
        #pragma unroll
        for (int w = 0; w < 8; w++) { int t = wsum[w]; wsum[w] = run; run += t; }
        g_off[N_NODES] = run;
    }
    __syncthreads();
    int off = wsum[wid] + texcl;
    #pragma unroll
    for (int j = 0; j < 8; j++) {
        int idx = base + j;
        if (idx < N_NODES) {
            int o = off + v[j];
            g_off[idx] = o; g_cur[idx] = o;
            g_cnt[idx] = 0;                    // reset for next call
        }
    }
    for (int i = tid; i < N_NODES; i += 256) {
        float d = 1.0f + g_deg[i];            // self-loop weight 1
        g_dis[i]    = rsqrtf(d);
        g_invdeg[i] = 1.0f / d;               // self-loop norm = dis*dis
        g_deg[i]    = 0.0f;                   // reset for next call
    }
}

__global__ void k_fill(const void* __restrict__ ei, const float* __restrict__ ew) {
    int e = blockIdx.x * blockDim.x + threadIdx.x;
    int valid = (e < N_EDGES);
    int is64 = detect_is64(ei, e, valid);
    if (valid) {
        int r = edge_row(ei, e, is64);
        int c = edge_col(ei, e, is64);
        if ((unsigned)r < N_NODES && (unsigned)c < N_NODES) {
            int p = atomicAdd(&g_cur[c], 1);
            if ((unsigned)p < N_EDGES) {
                g_src[p] = r;
                g_nrm[p] = g_dis[r] * ew[e] * g_dis[c];
            }
        }
    }
}

// ------------------------------------------------------------------
// Fused gated temporal conv + GCN weight matmul, row-pair-packed FFMA2.
// Block: 128 threads, tile 128 rows x 32 cols, one bt per blockIdx.y.
// Thread = 8 rows (4 f32x2 row-pairs) x 4 cols. x tiles stored PRE-PAIRED:
// xp[k][pair] float2 -> LDS.64 per pair. Weights: 1 LDS.128 (4 cols) per
// matrix per k, duplicated to (w,w) pairs in registers.
// smem bytes/thread/k = 32 (w) + 64 (x)  vs 128+8 before: ~2.2x less traffic.
__global__ void __launch_bounds__(128, 3) k_conv(
                       const float* __restrict__ x,
                       const float* __restrict__ w1, const float* __restrict__ b1,
                       const float* __restrict__ w2, const float* __restrict__ b2,
                       const float* __restrict__ gw) {
    extern __shared__ float sm[];
    // layout (floats): xp0 [32][XPS]f2 @0, xp2 @4160, w1a@8320, w1b, w2a, w2b, gws (1024 each)
    float* xp0 = sm;                    // packed pairs, also reused as g-tile
    float* xp2 = sm + 32 * XPS * 2;     // 4160
    float* w1a = xp2 + 32 * XPS * 2;    // [k][o]
    float* w1b = w1a + 1024;
    float* w2a = w1b + 1024;
    float* w2b = w2a + 1024;
    float* gws = w2b + 1024;
    __shared__ __align__(16) float bs1[32];
    __shared__ __align__(16) float bs2[32];

    int bt = blockIdx.y;
    int b = bt >> 5, t = bt & 31;
    int n0 = blockIdx.x * 128;
    int nrows = N_NODES - n0; if (nrows > 128) nrows = 128;
    int tid = threadIdx.x;

    for (int i = tid; i < 1024; i += 128) {
        int o = i & 31, cc = i >> 5;
        w1a[cc * 32 + o] = w1[o * 64 + cc * 2 + 0];
        w1b[cc * 32 + o] = w1[o * 64 + cc * 2 + 1];
        w2a[cc * 32 + o] = w2[o * 64 + cc * 2 + 0];
        w2b[cc * 32 + o] = w2[o * 64 + cc * 2 + 1];
        gws[i] = gw[i];
    }
    if (tid < 32) { bs1[tid] = b1[tid]; bs2[tid] = b2[tid]; }

    // Load x (LDG.128) and scatter into pair-packed layout:
    // float index = k*2*XPS + pair*2 + (row&1)
    const float4* x0v = (const float4*)(x + ((size_t)(b * 34 + t)     * N_NODES + n0) * C);
    const float4* x2v = (const float4*)(x + ((size_t)(b * 34 + t + 2) * N_NODES + n0) * C);
    const float4 z4 = make_float4(0.f, 0.f, 0.f, 0.f);
    for (int i = tid; i < 1024; i += 128) {        // 128 rows x 8 float4
        int r = i >> 3, c4 = (i & 7) * 4;
        float4 v = (r < nrows) ? x0v[i] : z4;
        float4 u = (r < nrows) ? x2v[i] : z4;
        int fb = (r >> 1) * 2 + (r & 1);           // pair*2 + half
        xp0[(c4 + 0) * (2 * XPS) + fb] = v.x;
        xp0[(c4 + 1) * (2 * XPS) + fb] = v.y;
        xp0[(c4 + 2) * (2 * XPS) + fb] = v.z;
        xp0[(c4 + 3) * (2 * XPS) + fb] = v.w;
        xp2[(c4 + 0) * (2 * XPS) + fb] = u.x;
        xp2[(c4 + 1) * (2 * XPS) + fb] = u.y;
        xp2[(c4 + 2) * (2 * XPS) + fb] = u.z;
        xp2[(c4 + 3) * (2 * XPS) + fb] = u.w;
    }
    __syncthreads();

    int cg = tid & 7;          // col group: 4 cols, co = cg*4
    int rg = tid >> 3;         // row group: 8 rows = 4 pairs, pair base rg*4
    int co = cg * 4;
    int pb = rg * 4;

    u64 acc1[4][4], acc2[4][4];    // [pair][col], halves = (row_even, row_odd)
    #pragma unroll
    for (int c = 0; c < 4; c++) {
        u64 v1 = pack2(bs1[co + c], bs1[co + c]);
        u64 v2 = pack2(bs2[co + c], bs2[co + c]);
        #pragma unroll
        for (int p = 0; p < 4; p++) { acc1[p][c] = v1; acc2[p][c] = v2; }
    }

    const float4* w1a4 = (const float4*)w1a;
    const float4* w1b4 = (const float4*)w1b;
    const float4* w2a4 = (const float4*)w2a;
    const float4* w2b4 = (const float4*)w2b;

    #pragma unroll 4
    for (int k = 0; k < 32; k++) {
        u64 xa[4], xb[4];
        #pragma unroll
        for (int p = 0; p < 4; p++) {
            xa[p] = *(const u64*)&xp0[k * (2 * XPS) + (pb + p) * 2];
            xb[p] = *(const u64*)&xp2[k * (2 * XPS) + (pb + p) * 2];
        }
        float4 f1a = w1a4[k * 8 + cg];
        float4 f1b = w1b4[k * 8 + cg];
        float4 f2a = w2a4[k * 8 + cg];
        float4 f2b = w2b4[k * 8 + cg];
        u64 d1a[4] = {pack2(f1a.x, f1a.x), pack2(f1a.y, f1a.y), pack2(f1a.z, f1a.z), pack2(f1a.w, f1a.w)};
        u64 d1b[4] = {pack2(f1b.x, f1b.x), pack2(f1b.y, f1b.y), pack2(f1b.z, f1b.z), pack2(f1b.w, f1b.w)};
        u64 d2a[4] = {pack2(f2a.x, f2a.x), pack2(f2a.y, f2a.y), pack2(f2a.z, f2a.z), pack2(f2a.w, f2a.w)};
        u64 d2b[4] = {pack2(f2b.x, f2b.x), pack2(f2b.y, f2b.y), pack2(f2b.z, f2b.z), pack2(f2b.w, f2b.w)};
        #pragma unroll
        for (int p = 0; p < 4; p++)
            #pragma unroll
            for (int c = 0; c < 4; c++) {
                acc1[p][c] = fma2(xa[p], d1a[c], acc1[p][c]);
                acc1[p][c] = fma2(xb[p], d1b[c], acc1[p][c]);
                acc2[p][c] = fma2(xa[p], d2a[c], acc2[p][c]);
                acc2[p][c] = fma2(xb[p], d2b[c], acc2[p][c]);
            }
    }

    __syncthreads();                 // xp0/xp2 reads done; reuse xp0 as packed g-tile
    // g = tanh(a1)*sigmoid(a2), stored pair-packed: gp[col][pair] at xp0
    #pragma unroll
    for (int p = 0; p < 4; p++) {
        #pragma unroll
        for (int c = 0; c < 4; c++) {
            float a0, a1v, s0, s1;
            unpack2(acc1[p][c], a0, a1v);
            unpack2(acc2[p][c], s0, s1);
            float th0 = 2.0f / (1.0f + __expf(-2.0f * a0)) - 1.0f;
            float th1 = 2.0f / (1.0f + __expf(-2.0f * a1v)) - 1.0f;
            float sg0 = 1.0f / (1.0f + __expf(-s0));
            float sg1 = 1.0f / (1.0f + __expf(-s1));
            *(u64*)&xp0[(co + c) * (2 * XPS) + (pb + p) * 2] =
                pack2(th0 * sg0, th1 * sg1);
        }
    }
    __syncthreads();

    u64 hacc[4][4];
    u64 z = pack2(0.0f, 0.0f);
    #pragma unroll
    for (int p = 0; p < 4; p++)
        #pragma unroll
        for (int c = 0; c < 4; c++) hacc[p][c] = z;

    const float4* gws4 = (const float4*)gws;
    #pragma unroll 4
    for (int k = 0; k < 32; k++) {
        u64 gp[4];
        #pragma unroll
        for (int p = 0; p < 4; p++)
            gp[p] = *(const u64*)&xp0[k * (2 * XPS) + (pb + p) * 2];
        float4 fg = gws4[k * 8 + cg];
        u64 dg[4] = {pack2(fg.x, fg.x), pack2(fg.y, fg.y), pack2(fg.z, fg.z), pack2(fg.w, fg.w)};
        #pragma unroll
        for (int p = 0; p < 4; p++)
            #pragma unroll
            for (int c = 0; c < 4; c++)
                hacc[p][c] = fma2(gp[p], dg[c], hacc[p][c]);
    }

    float* outp = g_hw + ((size_t)bt * N_NODES + n0) * C;
    #pragma unroll
    for (int p = 0; p < 4; p++) {
        int re = rg * 8 + 2 * p;       // even row
        float e0, o0, e1, o1, e2, o2, e3, o3;
        unpack2(hacc[p][0], e0, o0);
        unpack2(hacc[p][1], e1, o1);
        unpack2(hacc[p][2], e2, o2);
        unpack2(hacc[p][3], e3, o3);
        if (re < nrows)
            *(float4*)&outp[re * 32 + co] = make_float4(e0, e1, e2, e3);
        if (re + 1 < nrows)
            *(float4*)&outp[(re + 1) * 32 + co] = make_float4(o0, o1, o2, o3);
    }
}

// ------------------------------------------------------------------
// Gather: warp per (bt, dst). lane = (half, channel-pair): half-warps process
// different edges (4 edges/iter/warp via 2 accs each), float2 loads, final
// shfl_xor(16) cross-half reduce. hw slice per bt (256KB) is L2-resident.
__global__ void k_gather(const float* __restrict__ gb, float* __restrict__ out) {
    int w = (blockIdx.x * blockDim.x + threadIdx.x) >> 5;
    if (w >= NBT * N_NODES) return;
    int lane = threadIdx.x & 31;
    int half = lane >> 4;
    int hl   = lane & 15;
    int bt  = w / N_NODES;
    int dst = w - bt * N_NODES;
    const float2* hb = (const float2*)(g_hw + (size_t)bt * (N_NODES * C));

    float2 acc0 = make_float2(0.0f, 0.0f);
    float2 acc1 = make_float2(0.0f, 0.0f);
    if (half == 0) {
        float2 bv = ((const float2*)gb)[hl];
        float idg = g_invdeg[dst];
        float2 sv = hb[dst * 16 + hl];
        acc0.x = bv.x + idg * sv.x;
        acc0.y = bv.y + idg * sv.y;
    }

    int s = g_off[dst], e = g_off[dst + 1];
    int i = s;
    for (; i + 3 < e; i += 4) {
        int ia = i + half * 2, ib = ia + 1;
        int   sa = g_src[ia]; float na = g_nrm[ia];
        int   sb = g_src[ib]; float nb = g_nrm[ib];
        float2 va = hb[sa * 16 + hl];
        float2 vb = hb[sb * 16 + hl];
        acc0.x += na * va.x; acc0.y += na * va.y;
        acc1.x += nb * vb.x; acc1.y += nb * vb.y;
    }
    for (; i + 1 < e; i += 2) {
        int ia = i + half;
        int sa = g_src[ia]; float na = g_nrm[ia];
        float2 va = hb[sa * 16 + hl];
        acc0.x += na * va.x; acc0.y += na * va.y;
    }
    if (i < e && half == 0) {
        int sa = g_src[i]; float na = g_nrm[i];
        float2 va = hb[sa * 16 + hl];
        acc0.x += na * va.x; acc0.y += na * va.y;
    }

    float rx = acc0.x + acc1.x;
    float ry = acc0.y + acc1.y;
    rx += __shfl_xor_sync(0xffffffffu, rx, 16);
    ry += __shfl_xor_sync(0xffffffffu, ry, 16);
    if (half == 0)
        ((float2*)out)[(size_t)w * 16 + hl] = make_float2(rx, ry);
}

// ------------------------------------------------------------------
extern "C" void kernel_launch(void* const* d_in, const int* in_sizes, int n_in,
                              void* d_out, int out_size) {
    const float* x  = (const float*)d_in[0];
    const void*  ei = d_in[1];                 // int64 OR int32 — detected per-block
    const float* ew = (const float*)d_in[2];
    const float* w1 = (const float*)d_in[3];
    const float* b1 = (const float*)d_in[4];
    const float* w2 = (const float*)d_in[5];
    const float* b2 = (const float*)d_in[6];
    const float* gw = (const float*)d_in[7];
    const float* gb = (const float*)d_in[8];
    float* out = (float*)d_out;

    k_deg  <<<(N_EDGES + 255) / 256, 256>>>(ei, ew);
    k_scan <<<1, 256>>>();
    k_fill <<<(N_EDGES + 255) / 256, 256>>>(ei, ew);

    int smem = (2 * 32 * XPS * 2 + 5 * 1024) * (int)sizeof(float);   // 53760 B
    cudaFuncSetAttribute(k_conv, cudaFuncAttributeMaxDynamicSharedMemorySize, smem);
    dim3 grid(16, NBT);
    k_conv<<<grid, 128, smem>>>(x, w1, b1, w2, b2, gw);

    int totw = NBT * N_NODES;                        // 256000 warps
    k_gather<<<(totw * 32 + 255) / 256, 256>>>(gb, out);
}